// round 2
// baseline (speedup 1.0000x reference)
#include <cuda_runtime.h>
#include <math.h>

#define NBATCH 8192
#define CELLS  49
#define CH     30
#define ELEMS  (CELLS * CH)   // 1470
#define NBOX   98

// Per-block partial sums: [batch][4] = {cls, obj_conf, noobj, coord}
__device__ float g_partial[NBATCH * 4];

__global__ __launch_bounds__(256) void yolo_main(const float* __restrict__ pred,
                                                 const float* __restrict__ target)
{
    __shared__ float sp[ELEMS];
    __shared__ float st[ELEMS];
    __shared__ float px[NBOX][5];   // pred xyxy
    __shared__ float tx[NBOX][5];   // target xyxy
    __shared__ float cp[NBOX][5];   // compacted masked pred boxes: x0,y0,x1,y1,area
    __shared__ int   smask[NBOX];
    __shared__ int   pcount;
    __shared__ float wsum[8][4];

    const int b = blockIdx.x;
    const int t = threadIdx.x;

    // ---- Stage inputs (coalesced float2: 1470 floats = 735 float2 per tensor) ----
    {
        const float2* p2 = reinterpret_cast<const float2*>(pred   + (size_t)b * ELEMS);
        const float2* t2 = reinterpret_cast<const float2*>(target + (size_t)b * ELEMS);
        float2* sp2 = reinterpret_cast<float2*>(sp);
        float2* st2 = reinterpret_cast<float2*>(st);
        for (int i = t; i < ELEMS / 2; i += 256) { sp2[i] = p2[i]; st2[i] = t2[i]; }
    }
    if (t == 0) pcount = 0;
    __syncthreads();

    float l_cls = 0.f, l_noobj = 0.f;

    // ---- Per-cell work: noobj conf loss, class loss, box xyxy + mask ----
    for (int c = t; c < CELLS; c += 256) {
        const float* pc = sp + c * CH;
        const float* tc = st + c * CH;
        const float conf = tc[4];
        const bool obj = (conf > 0.f);

        if (conf == 0.f) {
            float d4 = pc[4] - tc[4];
            float d9 = pc[9] - tc[9];
            l_noobj += d4 * d4 + d9 * d9;
        }

        #pragma unroll
        for (int k = 0; k < 2; k++) {
            const int m = c * 2 + k;
            float cx = pc[k * 5 + 0], cy = pc[k * 5 + 1];
            float w  = pc[k * 5 + 2], h  = pc[k * 5 + 3];
            px[m][0] = cx - 0.5f * w;  px[m][1] = cy - 0.5f * h;
            px[m][2] = cx + 0.5f * w;  px[m][3] = cy + 0.5f * h;
            cx = tc[k * 5 + 0]; cy = tc[k * 5 + 1];
            w  = tc[k * 5 + 2]; h  = tc[k * 5 + 3];
            tx[m][0] = cx - 0.5f * w;  tx[m][1] = cy - 0.5f * h;
            tx[m][2] = cx + 0.5f * w;  tx[m][3] = cy + 0.5f * h;
            smask[m] = obj ? 1 : 0;
        }

        if (obj) {
            float s = 0.f;
            #pragma unroll
            for (int j = 10; j < 30; j++) {
                float d = pc[j] - tc[j];
                s += d * d;
            }
            l_cls += s;
        }
    }
    __syncthreads();

    // ---- Compact masked pred boxes (order-independent: consumed only by max) ----
    for (int m = t; m < NBOX; m += 256) {
        if (smask[m]) {
            int idx = atomicAdd(&pcount, 1);
            float x0 = px[m][0], y0 = px[m][1], x1 = px[m][2], y1 = px[m][3];
            cp[idx][0] = x0; cp[idx][1] = y0; cp[idx][2] = x1; cp[idx][3] = y1;
            cp[idx][4] = (x1 - x0) * (y1 - y0);
        }
    }
    __syncthreads();
    const int K = pcount;

    float l_obj = 0.f, l_coord = 0.f;

    // ---- Per masked target box: max IoU over compacted masked preds ----
    for (int m = t; m < NBOX; m += 256) {
        if (!smask[m]) continue;
        const float ax0 = tx[m][0], ay0 = tx[m][1], ax1 = tx[m][2], ay1 = tx[m][3];
        const float area_t = (ax1 - ax0) * (ay1 - ay0);
        float maxi = 0.f;
        for (int i = 0; i < K; i++) {
            float bx0 = cp[i][0], by0 = cp[i][1], bx1 = cp[i][2], by1 = cp[i][3];
            float area_p = cp[i][4];
            float iw = fminf(ax1, bx1) - fmaxf(ax0, bx0);
            float ih = fminf(ay1, by1) - fmaxf(ay0, by0);
            iw = fmaxf(iw, 0.f); ih = fmaxf(ih, 0.f);
            float inter = iw * ih;
            float uni = area_t + area_p - inter;
            float iou = inter / (uni > 0.f ? uni : 1.f);
            maxi = fmaxf(maxi, iou);
        }
        if (maxi != 0.f) {
            const int c = m >> 1, k = m & 1;
            const float* pp = sp + c * CH + k * 5;
            const float* tt = st + c * CH + k * 5;
            float dx = pp[0] - tt[0];
            float dy = pp[1] - tt[1];
            float dw = sqrtf(pp[2]) - sqrtf(tt[2]);
            float dh = sqrtf(pp[3]) - sqrtf(tt[3]);
            l_coord += dx * dx + dy * dy + dw * dw + dh * dh;
            float dc = pp[4] - tt[4];
            l_obj += dc * dc;
        }
    }

    // ---- Block reduction of 4 partials ----
    float v0 = l_cls, v1 = l_obj, v2 = l_noobj, v3 = l_coord;
    #pragma unroll
    for (int off = 16; off; off >>= 1) {
        v0 += __shfl_down_sync(0xffffffffu, v0, off);
        v1 += __shfl_down_sync(0xffffffffu, v1, off);
        v2 += __shfl_down_sync(0xffffffffu, v2, off);
        v3 += __shfl_down_sync(0xffffffffu, v3, off);
    }
    const int warp = t >> 5, lane = t & 31;
    if (lane == 0) { wsum[warp][0] = v0; wsum[warp][1] = v1; wsum[warp][2] = v2; wsum[warp][3] = v3; }
    __syncthreads();
    if (t == 0) {
        float s0 = 0.f, s1 = 0.f, s2 = 0.f, s3 = 0.f;
        #pragma unroll
        for (int w = 0; w < 8; w++) { s0 += wsum[w][0]; s1 += wsum[w][1]; s2 += wsum[w][2]; s3 += wsum[w][3]; }
        float* gp = &g_partial[b * 4];
        gp[0] = s0; gp[1] = s1; gp[2] = s2; gp[3] = s3;
    }
}

__global__ __launch_bounds__(256) void yolo_finalize(float* __restrict__ out)
{
    __shared__ double sh[256][4];
    const int t = threadIdx.x;
    double a0 = 0.0, a1 = 0.0, a2 = 0.0, a3 = 0.0;
    for (int i = t; i < NBATCH; i += 256) {
        const float* p = &g_partial[i * 4];
        a0 += (double)p[0]; a1 += (double)p[1]; a2 += (double)p[2]; a3 += (double)p[3];
    }
    sh[t][0] = a0; sh[t][1] = a1; sh[t][2] = a2; sh[t][3] = a3;
    __syncthreads();
    for (int s = 128; s; s >>= 1) {
        if (t < s) {
            sh[t][0] += sh[t + s][0];
            sh[t][1] += sh[t + s][1];
            sh[t][2] += sh[t + s][2];
            sh[t][3] += sh[t + s][3];
        }
        __syncthreads();
    }
    if (t == 0) {
        const double inv = 1.0 / (double)NBATCH;
        double cls   = sh[0][0] * inv;
        double obj   = (sh[0][1] + 0.5 * sh[0][2]) * inv;   // obj + NOOBJ_LAMBDA * noobj
        double coord = sh[0][3] * 5.0 * inv;                 // COORD_LAMBDA
        out[0] = (float)(cls + obj + coord);
        out[1] = (float)cls;
        out[2] = (float)obj;
        out[3] = (float)coord;
    }
}

extern "C" void kernel_launch(void* const* d_in, const int* in_sizes, int n_in,
                              void* d_out, int out_size)
{
    const float* pred   = (const float*)d_in[0];
    const float* target = (const float*)d_in[1];
    yolo_main<<<NBATCH, 256>>>(pred, target);
    yolo_finalize<<<1, 256>>>((float*)d_out);
}

// round 3
// speedup vs baseline: 1.1448x; 1.1448x over previous
#include <cuda_runtime.h>
#include <math.h>

#define NBATCH 8192
#define CELLS  49
#define CH     30
#define ELEMS  (CELLS * CH)   // 1470
#define NBOX   98
#define BT     128            // threads per block

__device__ float g_partial[NBATCH * 4];   // [batch][4] = {cls, obj, noobj, coord}
__device__ int   g_done = 0;              // ticket counter (reset by last CTA)

__global__ __launch_bounds__(BT) void yolo_fused(const float* __restrict__ pred,
                                                 const float* __restrict__ target,
                                                 float* __restrict__ out)
{
    __shared__ float sp[ELEMS];
    __shared__ float st[ELEMS];
    __shared__ float px[NBOX][4];   // pred xyxy
    __shared__ float tx[NBOX][4];   // target xyxy
    __shared__ float cp[NBOX][5];   // compacted masked pred boxes: x0,y0,x1,y1,area
    __shared__ int   smask[NBOX];
    __shared__ int   pcount;
    __shared__ float wsum[4][4];
    __shared__ double dsum[4][4];
    __shared__ bool  is_last;

    const int b = blockIdx.x;
    const int t = threadIdx.x;

    if (t == 0) pcount = 0;

    // ---- Stage inputs: 735 float2 per tensor, front-batched (MLP ~12) ----
    {
        const float2* p2 = reinterpret_cast<const float2*>(pred   + (size_t)b * ELEMS);
        const float2* t2 = reinterpret_cast<const float2*>(target + (size_t)b * ELEMS);
        float2* sp2 = reinterpret_cast<float2*>(sp);
        float2* st2 = reinterpret_cast<float2*>(st);
        float2 pa[6], ta[6];
        #pragma unroll
        for (int u = 0; u < 5; u++) { pa[u] = p2[t + u * BT]; ta[u] = t2[t + u * BT]; }
        const bool extra = (t < (735 - 5 * BT));   // 735 = 5*128 + 95
        if (extra) { pa[5] = p2[t + 5 * BT]; ta[5] = t2[t + 5 * BT]; }
        #pragma unroll
        for (int u = 0; u < 5; u++) { sp2[t + u * BT] = pa[u]; st2[t + u * BT] = ta[u]; }
        if (extra) { sp2[t + 5 * BT] = pa[5]; st2[t + 5 * BT] = ta[5]; }
    }
    __syncthreads();

    float l_cls = 0.f, l_noobj = 0.f;

    // ---- Phase 1: per-cell losses (t<49) + per-box xyxy/mask/compaction (t<98) ----
    if (t < CELLS) {
        const float* pc = sp + t * CH;
        const float* tc = st + t * CH;
        const float conf = tc[4];
        if (conf == 0.f) {
            float d4 = pc[4] - tc[4];
            float d9 = pc[9] - tc[9];
            l_noobj = d4 * d4 + d9 * d9;
        } else {   // conf > 0 (conf is exactly 0 or 1)
            float s = 0.f;
            #pragma unroll
            for (int j = 10; j < 30; j++) {
                float d = pc[j] - tc[j];
                s += d * d;
            }
            l_cls = s;
        }
    }
    if (t < NBOX) {
        const int c = t >> 1, k = t & 1;
        const float* pc = sp + c * CH + k * 5;
        const float* tc = st + c * CH + k * 5;
        const bool obj = (st[c * CH + 4] > 0.f);

        float cx = pc[0], cy = pc[1], w = pc[2], h = pc[3];
        float px0 = cx - 0.5f * w, py0 = cy - 0.5f * h;
        float px1 = cx + 0.5f * w, py1 = cy + 0.5f * h;
        px[t][0] = px0; px[t][1] = py0; px[t][2] = px1; px[t][3] = py1;

        cx = tc[0]; cy = tc[1]; w = tc[2]; h = tc[3];
        tx[t][0] = cx - 0.5f * w; tx[t][1] = cy - 0.5f * h;
        tx[t][2] = cx + 0.5f * w; tx[t][3] = cy + 0.5f * h;
        smask[t] = obj ? 1 : 0;

        if (obj) {   // compact masked pred boxes (order-independent: consumed only by max)
            int idx = atomicAdd(&pcount, 1);
            cp[idx][0] = px0; cp[idx][1] = py0; cp[idx][2] = px1; cp[idx][3] = py1;
            cp[idx][4] = (px1 - px0) * (py1 - py0);
        }
    }
    __syncthreads();
    const int K = pcount;

    float l_obj = 0.f, l_coord = 0.f;

    // ---- Phase 2: per masked target box, max IoU over compacted masked preds ----
    if (t < NBOX && smask[t]) {
        const float ax0 = tx[t][0], ay0 = tx[t][1], ax1 = tx[t][2], ay1 = tx[t][3];
        const float area_t = (ax1 - ax0) * (ay1 - ay0);
        float maxi = 0.f;
        for (int i = 0; i < K; i++) {
            float iw = fminf(ax1, cp[i][2]) - fmaxf(ax0, cp[i][0]);
            float ih = fminf(ay1, cp[i][3]) - fmaxf(ay0, cp[i][1]);
            iw = fmaxf(iw, 0.f); ih = fmaxf(ih, 0.f);
            float inter = iw * ih;
            float uni = area_t + cp[i][4] - inter;
            float iou = inter / (uni > 0.f ? uni : 1.f);
            maxi = fmaxf(maxi, iou);
        }
        if (maxi != 0.f) {
            const int c = t >> 1, k = t & 1;
            const float* pp = sp + c * CH + k * 5;
            const float* tt = st + c * CH + k * 5;
            float dx = pp[0] - tt[0];
            float dy = pp[1] - tt[1];
            float dw = sqrtf(pp[2]) - sqrtf(tt[2]);
            float dh = sqrtf(pp[3]) - sqrtf(tt[3]);
            l_coord = dx * dx + dy * dy + dw * dw + dh * dh;
            float dc = pp[4] - tt[4];
            l_obj = dc * dc;
        }
    }

    // ---- Block reduction of 4 partials (4 warps) ----
    float v0 = l_cls, v1 = l_obj, v2 = l_noobj, v3 = l_coord;
    #pragma unroll
    for (int off = 16; off; off >>= 1) {
        v0 += __shfl_down_sync(0xffffffffu, v0, off);
        v1 += __shfl_down_sync(0xffffffffu, v1, off);
        v2 += __shfl_down_sync(0xffffffffu, v2, off);
        v3 += __shfl_down_sync(0xffffffffu, v3, off);
    }
    const int warp = t >> 5, lane = t & 31;
    if (lane == 0) { wsum[warp][0] = v0; wsum[warp][1] = v1; wsum[warp][2] = v2; wsum[warp][3] = v3; }
    __syncthreads();

    if (t == 0) {
        float s0 = 0.f, s1 = 0.f, s2 = 0.f, s3 = 0.f;
        #pragma unroll
        for (int w = 0; w < 4; w++) { s0 += wsum[w][0]; s1 += wsum[w][1]; s2 += wsum[w][2]; s3 += wsum[w][3]; }
        float* gp = &g_partial[b * 4];
        gp[0] = s0; gp[1] = s1; gp[2] = s2; gp[3] = s3;
        __threadfence();                                  // publish partials
        int ticket = atomicAdd(&g_done, 1);
        is_last = (ticket == NBATCH - 1);
    }
    __syncthreads();

    // ---- Last CTA: global finalize (deterministic fixed-order sum) ----
    if (is_last) {
        if (t == 0) g_done = 0;                           // reset for next graph replay
        const float4* gp4 = reinterpret_cast<const float4*>(g_partial);
        double a0 = 0.0, a1 = 0.0, a2 = 0.0, a3 = 0.0;
        #pragma unroll 8
        for (int i = t; i < NBATCH; i += BT) {
            float4 v = __ldcg(&gp4[i]);                   // bypass (incoherent) L1
            a0 += (double)v.x; a1 += (double)v.y; a2 += (double)v.z; a3 += (double)v.w;
        }
        #pragma unroll
        for (int off = 16; off; off >>= 1) {
            a0 += __shfl_down_sync(0xffffffffu, a0, off);
            a1 += __shfl_down_sync(0xffffffffu, a1, off);
            a2 += __shfl_down_sync(0xffffffffu, a2, off);
            a3 += __shfl_down_sync(0xffffffffu, a3, off);
        }
        if (lane == 0) { dsum[warp][0] = a0; dsum[warp][1] = a1; dsum[warp][2] = a2; dsum[warp][3] = a3; }
        __syncthreads();
        if (t == 0) {
            double s0 = 0.0, s1 = 0.0, s2 = 0.0, s3 = 0.0;
            #pragma unroll
            for (int w = 0; w < 4; w++) { s0 += dsum[w][0]; s1 += dsum[w][1]; s2 += dsum[w][2]; s3 += dsum[w][3]; }
            const double inv = 1.0 / (double)NBATCH;
            double cls   = s0 * inv;
            double obj   = (s1 + 0.5 * s2) * inv;         // obj + NOOBJ_LAMBDA * noobj
            double coord = s3 * 5.0 * inv;                // COORD_LAMBDA
            out[0] = (float)(cls + obj + coord);
            out[1] = (float)cls;
            out[2] = (float)obj;
            out[3] = (float)coord;
        }
    }
}

extern "C" void kernel_launch(void* const* d_in, const int* in_sizes, int n_in,
                              void* d_out, int out_size)
{
    const float* pred   = (const float*)d_in[0];
    const float* target = (const float*)d_in[1];
    yolo_fused<<<NBATCH, BT>>>(pred, target, (float*)d_out);
}